// round 6
// baseline (speedup 1.0000x reference)
#include <cuda_runtime.h>
#include <cstdint>

#define L  2
#define T  128
#define NB 64      // batch N
#define H  512
#define E  256
#define A  200
#define V  1000
#define S  40
#define LT (L*T)   // 256
#define KIN0 (E+H) // 768

// ---------------- scratch (device globals) ----------------
__device__ __align__(16) float g_Kproj[L*T*NB*A];    // (l,t,n,a)
__device__ __align__(16) float g_qproj[L*NB*A];      // (l,n,a)
__device__ __align__(16) float g_scores[NB*LT];      // (n, lt)
__device__ __align__(16) float g_x[(E+H)*NB];        // (k,n)
__device__ __align__(16) float g_h[2][L][H*NB];      // [pingpong][layer][(k,n)]
__device__ __align__(16) float g_proj[H*NB];         // (k,n)
__device__ unsigned g_bar_count;
__device__ volatile unsigned g_bar_gen;

// ---------------- grid barrier (all blocks resident: grid == #SMs, 1 blk/SM) ----
__device__ __forceinline__ void grid_sync(int nb) {
    __syncthreads();
    if (threadIdx.x == 0) {
        __threadfence();
        unsigned gen = g_bar_gen;
        unsigned arrived = atomicAdd(&g_bar_count, 1u);
        if (arrived == (unsigned)nb - 1u) {
            g_bar_count = 0u;
            __threadfence();
            g_bar_gen = gen + 1u;
        } else {
            while (g_bar_gen == gen) { __nanosleep(32); }
        }
        __threadfence();
    }
    __syncthreads();
}

// ---------------- MUFU-free fast math ----------------
__device__ __forceinline__ float fast_rcp(float q) {
    float r = __uint_as_float(0x7EF311C3u - __float_as_uint(q));
    r = r * (2.0f - q * r);
    r = r * (2.0f - q * r);
    r = r * (2.0f - q * r);
    return r;
}

__device__ __forceinline__ float tanh_fast(float x) {
    const float c = 7.99881172180175781f;
    x = fminf(fmaxf(x, -c), c);
    float x2 = x * x;
    float p = fmaf(x2, -2.76076847742355e-16f, 2.00018790482477e-13f);
    p = fmaf(x2, p, -8.60467152213735e-11f);
    p = fmaf(x2, p,  5.12229709037114e-08f);
    p = fmaf(x2, p,  1.48572235717979e-05f);
    p = fmaf(x2, p,  6.37261928875436e-04f);
    p = fmaf(x2, p,  4.89352455891786e-03f);
    p = p * x;
    float q = fmaf(x2, 1.19825839466702e-06f, 1.18534705686654e-04f);
    q = fmaf(x2, q, 2.26843463243900e-03f);
    q = fmaf(x2, q, 4.89352518554385e-03f);
    return p * fast_rcp(q);
}

__device__ __forceinline__ float sigmoid_fast(float x) {
    return fmaf(tanh_fast(0.5f * x), 0.5f, 0.5f);
}

// ---------------- prep kernels ----------------
__global__ void prep_hinit(const float* __restrict__ efs) {
    int i = blockIdx.x * 256 + threadIdx.x;        // over L*NB*H
    if (i >= L * NB * H) return;
    int k = i % H;
    int n = (i / H) % NB;
    int l = i / (NB * H);
    g_h[0][l][k * NB + n] = efs[i];
}

__global__ void kproj_gemm(const float* __restrict__ eo,
                           const float* __restrict__ Kw,
                           const float* __restrict__ Kb) {
    const int l   = blockIdx.z;
    const int tn0 = blockIdx.x * 64;
    const int a0  = blockIdx.y * 64;
    const float* Ab = eo + (size_t)l * (T * NB) * H;
    const float* Bb = Kw + (size_t)l * A * H;
    __shared__ float As[16][64];
    __shared__ float Bs[16][64];
    const int tid = threadIdx.x;
    const int tr = tid >> 4, tc = tid & 15;
    const int lr = tid >> 2;
    const int lk = (tid & 3) * 4;
    float acc[4][4];
    #pragma unroll
    for (int i = 0; i < 4; i++)
        #pragma unroll
        for (int j = 0; j < 4; j++) acc[i][j] = 0.0f;

    for (int k0 = 0; k0 < H; k0 += 16) {
        float4 a4 = *reinterpret_cast<const float4*>(&Ab[(size_t)(tn0 + lr) * H + k0 + lk]);
        As[lk + 0][lr] = a4.x; As[lk + 1][lr] = a4.y;
        As[lk + 2][lr] = a4.z; As[lk + 3][lr] = a4.w;
        float4 b4 = make_float4(0.f, 0.f, 0.f, 0.f);
        if (a0 + lr < A)
            b4 = *reinterpret_cast<const float4*>(&Bb[(size_t)(a0 + lr) * H + k0 + lk]);
        Bs[lk + 0][lr] = b4.x; Bs[lk + 1][lr] = b4.y;
        Bs[lk + 2][lr] = b4.z; Bs[lk + 3][lr] = b4.w;
        __syncthreads();
        #pragma unroll
        for (int kk = 0; kk < 16; kk++) {
            float4 av = *reinterpret_cast<const float4*>(&As[kk][tr * 4]);
            float4 bv = *reinterpret_cast<const float4*>(&Bs[kk][tc * 4]);
            acc[0][0]=fmaf(av.x,bv.x,acc[0][0]); acc[0][1]=fmaf(av.x,bv.y,acc[0][1]);
            acc[0][2]=fmaf(av.x,bv.z,acc[0][2]); acc[0][3]=fmaf(av.x,bv.w,acc[0][3]);
            acc[1][0]=fmaf(av.y,bv.x,acc[1][0]); acc[1][1]=fmaf(av.y,bv.y,acc[1][1]);
            acc[1][2]=fmaf(av.y,bv.z,acc[1][2]); acc[1][3]=fmaf(av.y,bv.w,acc[1][3]);
            acc[2][0]=fmaf(av.z,bv.x,acc[2][0]); acc[2][1]=fmaf(av.z,bv.y,acc[2][1]);
            acc[2][2]=fmaf(av.z,bv.z,acc[2][2]); acc[2][3]=fmaf(av.z,bv.w,acc[2][3]);
            acc[3][0]=fmaf(av.w,bv.x,acc[3][0]); acc[3][1]=fmaf(av.w,bv.y,acc[3][1]);
            acc[3][2]=fmaf(av.w,bv.z,acc[3][2]); acc[3][3]=fmaf(av.w,bv.w,acc[3][3]);
        }
        __syncthreads();
    }
    #pragma unroll
    for (int i = 0; i < 4; i++) {
        int tn = tn0 + tr * 4 + i;
        #pragma unroll
        for (int j = 0; j < 4; j++) {
            int a = a0 + tc * 4 + j;
            if (a < A)
                g_Kproj[(size_t)(l * T * NB + tn) * A + a] = acc[i][j] + Kb[l * A + a];
        }
    }
}

// ---------------- GRU phase helper (in-warp split-K, interleaved k) ----------------
template <int KINP>
__device__ __forceinline__ void gru_phase(
    const float* __restrict__ Wih, const float* __restrict__ Whh,
    const float* __restrict__ bih, const float* __restrict__ bhh,
    const float* __restrict__ xin, const float* __restrict__ hin,
    float* __restrict__ hout, int gtid, int nthr)
{
    for (int t = gtid; t < H * 16 * 8; t += nthr) {
        int ks = t & 7;
        int nq = (t >> 3) & 15;
        int j  = t >> 7;
        int n0 = nq * 4;
        const float* wr = Wih + (size_t)j * KINP;
        const float* wz = wr + (size_t)H * KINP;
        const float* wn = wz + (size_t)H * KINP;
        const float* vr = Whh + (size_t)j * H;
        const float* vz = vr + (size_t)H * H;
        const float* vn = vz + (size_t)H * H;
        float ar[4] = {0,0,0,0}, az[4] = {0,0,0,0};
        float ai[4] = {0,0,0,0}, ah[4] = {0,0,0,0};
        // x segment (interleaved split-K: lane group covers k = ks*4 + 32*i)
        for (int k = ks * 4; k < KINP; k += 32) {
            float4 wR = *(const float4*)(wr + k);
            float4 wZ = *(const float4*)(wz + k);
            float4 wN = *(const float4*)(wn + k);
            float4 x0 = *(const float4*)(&xin[(k + 0) * NB + n0]);
            float4 x1 = *(const float4*)(&xin[(k + 1) * NB + n0]);
            float4 x2 = *(const float4*)(&xin[(k + 2) * NB + n0]);
            float4 x3 = *(const float4*)(&xin[(k + 3) * NB + n0]);
            ar[0]=fmaf(wR.x,x0.x,ar[0]); ar[1]=fmaf(wR.x,x0.y,ar[1]); ar[2]=fmaf(wR.x,x0.z,ar[2]); ar[3]=fmaf(wR.x,x0.w,ar[3]);
            ar[0]=fmaf(wR.y,x1.x,ar[0]); ar[1]=fmaf(wR.y,x1.y,ar[1]); ar[2]=fmaf(wR.y,x1.z,ar[2]); ar[3]=fmaf(wR.y,x1.w,ar[3]);
            ar[0]=fmaf(wR.z,x2.x,ar[0]); ar[1]=fmaf(wR.z,x2.y,ar[1]); ar[2]=fmaf(wR.z,x2.z,ar[2]); ar[3]=fmaf(wR.z,x2.w,ar[3]);
            ar[0]=fmaf(wR.w,x3.x,ar[0]); ar[1]=fmaf(wR.w,x3.y,ar[1]); ar[2]=fmaf(wR.w,x3.z,ar[2]); ar[3]=fmaf(wR.w,x3.w,ar[3]);
            az[0]=fmaf(wZ.x,x0.x,az[0]); az[1]=fmaf(wZ.x,x0.y,az[1]); az[2]=fmaf(wZ.x,x0.z,az[2]); az[3]=fmaf(wZ.x,x0.w,az[3]);
            az[0]=fmaf(wZ.y,x1.x,az[0]); az[1]=fmaf(wZ.y,x1.y,az[1]); az[2]=fmaf(wZ.y,x1.z,az[2]); az[3]=fmaf(wZ.y,x1.w,az[3]);
            az[0]=fmaf(wZ.z,x2.x,az[0]); az[1]=fmaf(wZ.z,x2.y,az[1]); az[2]=fmaf(wZ.z,x2.z,az[2]); az[3]=fmaf(wZ.z,x2.w,az[3]);
            az[0]=fmaf(wZ.w,x3.x,az[0]); az[1]=fmaf(wZ.w,x3.y,az[1]); az[2]=fmaf(wZ.w,x3.z,az[2]); az[3]=fmaf(wZ.w,x3.w,az[3]);
            ai[0]=fmaf(wN.x,x0.x,ai[0]); ai[1]=fmaf(wN.x,x0.y,ai[1]); ai[2]=fmaf(wN.x,x0.z,ai[2]); ai[3]=fmaf(wN.x,x0.w,ai[3]);
            ai[0]=fmaf(wN.y,x1.x,ai[0]); ai[1]=fmaf(wN.y,x1.y,ai[1]); ai[2]=fmaf(wN.y,x1.z,ai[2]); ai[3]=fmaf(wN.y,x1.w,ai[3]);
            ai[0]=fmaf(wN.z,x2.x,ai[0]); ai[1]=fmaf(wN.z,x2.y,ai[1]); ai[2]=fmaf(wN.z,x2.z,ai[2]); ai[3]=fmaf(wN.z,x2.w,ai[3]);
            ai[0]=fmaf(wN.w,x3.x,ai[0]); ai[1]=fmaf(wN.w,x3.y,ai[1]); ai[2]=fmaf(wN.w,x3.z,ai[2]); ai[3]=fmaf(wN.w,x3.w,ai[3]);
        }
        // h segment
        for (int k = ks * 4; k < H; k += 32) {
            float4 wR = *(const float4*)(vr + k);
            float4 wZ = *(const float4*)(vz + k);
            float4 wN = *(const float4*)(vn + k);
            float4 x0 = *(const float4*)(&hin[(k + 0) * NB + n0]);
            float4 x1 = *(const float4*)(&hin[(k + 1) * NB + n0]);
            float4 x2 = *(const float4*)(&hin[(k + 2) * NB + n0]);
            float4 x3 = *(const float4*)(&hin[(k + 3) * NB + n0]);
            ar[0]=fmaf(wR.x,x0.x,ar[0]); ar[1]=fmaf(wR.x,x0.y,ar[1]); ar[2]=fmaf(wR.x,x0.z,ar[2]); ar[3]=fmaf(wR.x,x0.w,ar[3]);
            ar[0]=fmaf(wR.y,x1.x,ar[0]); ar[1]=fmaf(wR.y,x1.y,ar[1]); ar[2]=fmaf(wR.y,x1.z,ar[2]); ar[3]=fmaf(wR.y,x1.w,ar[3]);
            ar[0]=fmaf(wR.z,x2.x,ar[0]); ar[1]=fmaf(wR.z,x2.y,ar[1]); ar[2]=fmaf(wR.z,x2.z,ar[2]); ar[3]=fmaf(wR.z,x2.w,ar[3]);
            ar[0]=fmaf(wR.w,x3.x,ar[0]); ar[1]=fmaf(wR.w,x3.y,ar[1]); ar[2]=fmaf(wR.w,x3.z,ar[2]); ar[3]=fmaf(wR.w,x3.w,ar[3]);
            az[0]=fmaf(wZ.x,x0.x,az[0]); az[1]=fmaf(wZ.x,x0.y,az[1]); az[2]=fmaf(wZ.x,x0.z,az[2]); az[3]=fmaf(wZ.x,x0.w,az[3]);
            az[0]=fmaf(wZ.y,x1.x,az[0]); az[1]=fmaf(wZ.y,x1.y,az[1]); az[2]=fmaf(wZ.y,x1.z,az[2]); az[3]=fmaf(wZ.y,x1.w,az[3]);
            az[0]=fmaf(wZ.z,x2.x,az[0]); az[1]=fmaf(wZ.z,x2.y,az[1]); az[2]=fmaf(wZ.z,x2.z,az[2]); az[3]=fmaf(wZ.z,x2.w,az[3]);
            az[0]=fmaf(wZ.w,x3.x,az[0]); az[1]=fmaf(wZ.w,x3.y,az[1]); az[2]=fmaf(wZ.w,x3.z,az[2]); az[3]=fmaf(wZ.w,x3.w,az[3]);
            ah[0]=fmaf(wN.x,x0.x,ah[0]); ah[1]=fmaf(wN.x,x0.y,ah[1]); ah[2]=fmaf(wN.x,x0.z,ah[2]); ah[3]=fmaf(wN.x,x0.w,ah[3]);
            ah[0]=fmaf(wN.y,x1.x,ah[0]); ah[1]=fmaf(wN.y,x1.y,ah[1]); ah[2]=fmaf(wN.y,x1.z,ah[2]); ah[3]=fmaf(wN.y,x1.w,ah[3]);
            ah[0]=fmaf(wN.z,x2.x,ah[0]); ah[1]=fmaf(wN.z,x2.y,ah[1]); ah[2]=fmaf(wN.z,x2.z,ah[2]); ah[3]=fmaf(wN.z,x2.w,ah[3]);
            ah[0]=fmaf(wN.w,x3.x,ah[0]); ah[1]=fmaf(wN.w,x3.y,ah[1]); ah[2]=fmaf(wN.w,x3.z,ah[2]); ah[3]=fmaf(wN.w,x3.w,ah[3]);
        }
        // in-warp split-K reduce over 8 lanes
        #pragma unroll
        for (int off = 4; off >= 1; off >>= 1) {
            #pragma unroll
            for (int i = 0; i < 4; i++) {
                ar[i] += __shfl_xor_sync(0xFFFFFFFFu, ar[i], off, 8);
                az[i] += __shfl_xor_sync(0xFFFFFFFFu, az[i], off, 8);
                ai[i] += __shfl_xor_sync(0xFFFFFFFFu, ai[i], off, 8);
                ah[i] += __shfl_xor_sync(0xFFFFFFFFu, ah[i], off, 8);
            }
        }
        if (ks == 0) {
            float br = bih[j] + bhh[j];
            float bz = bih[H + j] + bhh[H + j];
            float bi = bih[2 * H + j];
            float bh = bhh[2 * H + j];
            #pragma unroll
            for (int i = 0; i < 4; i++) {
                float r = sigmoid_fast(ar[i] + br);
                float z = sigmoid_fast(az[i] + bz);
                float nn = tanh_fast(ai[i] + bi + r * (ah[i] + bh));
                float hp = hin[j * NB + n0 + i];
                hout[j * NB + n0 + i] = fmaf(z, hp - nn, nn);
            }
        }
    }
}

// ---------------- the persistent decode kernel ----------------
__global__ void __launch_bounds__(512, 1)
decode_all(const float* __restrict__ eo, const int* __restrict__ targets,
           const float* __restrict__ embW,
           const float* __restrict__ Qw, const float* __restrict__ Qb,
           const float* __restrict__ Vw, const float* __restrict__ Vb,
           const float* __restrict__ Wih0, const float* __restrict__ Whh0,
           const float* __restrict__ bih0, const float* __restrict__ bhh0,
           const float* __restrict__ Wih1, const float* __restrict__ Whh1,
           const float* __restrict__ bih1, const float* __restrict__ bhh1,
           const float* __restrict__ Pw0, const float* __restrict__ Pb0,
           const float* __restrict__ Pw1, const float* __restrict__ Pb1,
           float* __restrict__ out)
{
    const int nb   = gridDim.x;
    const int tid  = threadIdx.x;
    const int gtid = blockIdx.x * 512 + tid;
    const int nthr = nb * 512;
    const int lane = tid & 31;

    __shared__ float smw[LT];
    __shared__ float sred[32];

    for (int s = 0; s < S; s++) {
        const int cur = s & 1;
        const int nxt = cur ^ 1;

        // ---- phase 1: qproj (tasks (l,a,nq) x ks8) ----
        for (int t = gtid; t < L * A * 16 * 8; t += nthr) {
            int ks = t & 7;
            int nq = (t >> 3) & 15;
            int r  = t >> 7;                 // l*A + a
            int a  = r % A, l = r / A;
            int n0 = nq * 4;
            const float* hp = g_h[cur][l];
            const float* w  = Qw + (size_t)r * H;
            float a0 = 0.f, a1 = 0.f, a2 = 0.f, a3 = 0.f;
            for (int k = ks * 4; k < H; k += 32) {
                float4 wv = *(const float4*)(w + k);
                float4 h0 = *(const float4*)(&hp[(k + 0) * NB + n0]);
                float4 h1 = *(const float4*)(&hp[(k + 1) * NB + n0]);
                float4 h2 = *(const float4*)(&hp[(k + 2) * NB + n0]);
                float4 h3 = *(const float4*)(&hp[(k + 3) * NB + n0]);
                a0=fmaf(wv.x,h0.x,a0); a1=fmaf(wv.x,h0.y,a1); a2=fmaf(wv.x,h0.z,a2); a3=fmaf(wv.x,h0.w,a3);
                a0=fmaf(wv.y,h1.x,a0); a1=fmaf(wv.y,h1.y,a1); a2=fmaf(wv.y,h1.z,a2); a3=fmaf(wv.y,h1.w,a3);
                a0=fmaf(wv.z,h2.x,a0); a1=fmaf(wv.z,h2.y,a1); a2=fmaf(wv.z,h2.z,a2); a3=fmaf(wv.z,h2.w,a3);
                a0=fmaf(wv.w,h3.x,a0); a1=fmaf(wv.w,h3.y,a1); a2=fmaf(wv.w,h3.z,a2); a3=fmaf(wv.w,h3.w,a3);
            }
            #pragma unroll
            for (int off = 4; off >= 1; off >>= 1) {
                a0 += __shfl_xor_sync(0xFFFFFFFFu, a0, off, 8);
                a1 += __shfl_xor_sync(0xFFFFFFFFu, a1, off, 8);
                a2 += __shfl_xor_sync(0xFFFFFFFFu, a2, off, 8);
                a3 += __shfl_xor_sync(0xFFFFFFFFu, a3, off, 8);
            }
            if (ks == 0) {
                float b = Qb[r];
                g_qproj[((size_t)l * NB + n0 + 0) * A + a] = a0 + b;
                g_qproj[((size_t)l * NB + n0 + 1) * A + a] = a1 + b;
                g_qproj[((size_t)l * NB + n0 + 2) * A + a] = a2 + b;
                g_qproj[((size_t)l * NB + n0 + 3) * A + a] = a3 + b;
            }
        }
        grid_sync(nb);

        // ---- phase 2: scores (warp-tasks (lt, ngroup of 8)) ----
        {
            int gw = gtid >> 5, nw = nthr >> 5;
            for (int wt = gw; wt < LT * 8; wt += nw) {
                int ng = wt & 7;
                int lt = wt >> 3;
                int l  = lt >> 7;            // / T
                int nbase = ng * 8;
                float acc[8] = {0,0,0,0,0,0,0,0};
                for (int i = 0; i < 7; i++) {
                    int a = i * 32 + lane;
                    if (a < A) {
                        float v = Vw[l * A + a];
                        #pragma unroll
                        for (int q = 0; q < 8; q++) {
                            int n = nbase + q;
                            float xq = g_qproj[((size_t)l * NB + n) * A + a]
                                     + g_Kproj[((size_t)lt * NB + n) * A + a];
                            acc[q] = fmaf(v, tanh_fast(xq), acc[q]);
                        }
                    }
                }
                #pragma unroll
                for (int q = 0; q < 8; q++) {
                    #pragma unroll
                    for (int off = 16; off >= 1; off >>= 1)
                        acc[q] += __shfl_down_sync(0xFFFFFFFFu, acc[q], off);
                }
                if (lane == 0) {
                    float vb = Vb[l];
                    #pragma unroll
                    for (int q = 0; q < 8; q++)
                        g_scores[(nbase + q) * LT + lt] = acc[q] + vb;
                }
            }
        }
        grid_sync(nb);

        // ---- phase 3: softmax + context + embedding (block-tasks (n, half)) ----
        for (int bt = blockIdx.x; bt < NB * 2; bt += nb) {
            int n = bt >> 1, half = bt & 1;
            float sc = (tid < LT) ? g_scores[n * LT + tid] : -3.4e38f;
            float m = sc;
            #pragma unroll
            for (int off = 16; off >= 1; off >>= 1)
                m = fmaxf(m, __shfl_xor_sync(0xFFFFFFFFu, m, off));
            if (lane == 0) sred[tid >> 5] = m;
            __syncthreads();
            if (tid < 16) {
                float v = sred[tid];
                #pragma unroll
                for (int off = 8; off >= 1; off >>= 1)
                    v = fmaxf(v, __shfl_xor_sync(0xFFFFu, v, off, 16));
                if (tid == 0) sred[0] = v;
            }
            __syncthreads();
            float mx = sred[0];
            float e = (tid < LT) ? __expf(sc - mx) : 0.f;
            float su = e;
            #pragma unroll
            for (int off = 16; off >= 1; off >>= 1)
                su += __shfl_xor_sync(0xFFFFFFFFu, su, off);
            __syncthreads();
            if (lane == 0) sred[tid >> 5] = su;
            __syncthreads();
            if (tid < 16) {
                float v = sred[tid];
                #pragma unroll
                for (int off = 8; off >= 1; off >>= 1)
                    v += __shfl_xor_sync(0xFFFFu, v, off, 16);
                if (tid == 0) sred[0] = v;
            }
            __syncthreads();
            float inv = 1.0f / sred[0];
            if (tid < LT) smw[tid] = e * inv;
            __syncthreads();
            if (tid < 256) {
                int h = half * 256 + tid;
                const float* ep = eo + (size_t)n * H + h;
                float acc = 0.f;
                #pragma unroll 8
                for (int lt2 = 0; lt2 < LT; lt2++)
                    acc = fmaf(smw[lt2], ep[(size_t)lt2 * (NB * H)], acc);
                g_x[(E + h) * NB + n] = acc;
            }
            if (half == 0 && tid < E) {
                int tok = (s == 0) ? 1 : targets[n * S + (s - 1)];
                g_x[tid * NB + n] = fmaxf(embW[(size_t)tok * E + tid], 0.f);
            }
            __syncthreads();
        }
        grid_sync(nb);

        // ---- phase 4: GRU layer 0 ----
        gru_phase<KIN0>(Wih0, Whh0, bih0, bhh0, g_x, g_h[cur][0], g_h[nxt][0], gtid, nthr);
        grid_sync(nb);

        // ---- phase 5: GRU layer 1 ----
        gru_phase<H>(Wih1, Whh1, bih1, bhh1, g_h[nxt][0], g_h[cur][1], g_h[nxt][1], gtid, nthr);
        grid_sync(nb);

        // ---- phase 6: proj (tasks (j,nq) x ks8) ----
        for (int t = gtid; t < H * 16 * 8; t += nthr) {
            int ks = t & 7;
            int nq = (t >> 3) & 15;
            int j  = t >> 7;
            int n0 = nq * 4;
            const float* w = Pw0 + (size_t)j * H;
            const float* h1 = g_h[nxt][1];
            float a0 = 0.f, a1 = 0.f, a2 = 0.f, a3 = 0.f;
            for (int k = ks * 4; k < H; k += 32) {
                float4 wv = *(const float4*)(w + k);
                float4 x0 = *(const float4*)(&h1[(k + 0) * NB + n0]);
                float4 x1 = *(const float4*)(&h1[(k + 1) * NB + n0]);
                float4 x2 = *(const float4*)(&h1[(k + 2) * NB + n0]);
                float4 x3 = *(const float4*)(&h1[(k + 3) * NB + n0]);
                a0=fmaf(wv.x,x0.x,a0); a1=fmaf(wv.x,x0.y,a1); a2=fmaf(wv.x,x0.z,a2); a3=fmaf(wv.x,x0.w,a3);
                a0=fmaf(wv.y,x1.x,a0); a1=fmaf(wv.y,x1.y,a1); a2=fmaf(wv.y,x1.z,a2); a3=fmaf(wv.y,x1.w,a3);
                a0=fmaf(wv.z,x2.x,a0); a1=fmaf(wv.z,x2.y,a1); a2=fmaf(wv.z,x2.z,a2); a3=fmaf(wv.z,x2.w,a3);
                a0=fmaf(wv.w,x3.x,a0); a1=fmaf(wv.w,x3.y,a1); a2=fmaf(wv.w,x3.z,a2); a3=fmaf(wv.w,x3.w,a3);
            }
            #pragma unroll
            for (int off = 4; off >= 1; off >>= 1) {
                a0 += __shfl_xor_sync(0xFFFFFFFFu, a0, off, 8);
                a1 += __shfl_xor_sync(0xFFFFFFFFu, a1, off, 8);
                a2 += __shfl_xor_sync(0xFFFFFFFFu, a2, off, 8);
                a3 += __shfl_xor_sync(0xFFFFFFFFu, a3, off, 8);
            }
            if (ks == 0) {
                float b = Pb0[j];
                g_proj[j * NB + n0 + 0] = fmaxf(a0 + b, 0.f);
                g_proj[j * NB + n0 + 1] = fmaxf(a1 + b, 0.f);
                g_proj[j * NB + n0 + 2] = fmaxf(a2 + b, 0.f);
                g_proj[j * NB + n0 + 3] = fmaxf(a3 + b, 0.f);
            }
        }
        grid_sync(nb);

        // ---- phase 7: logits (tasks (v,nq) x ks4) -> out ----
        for (int t = gtid; t < V * 16 * 4; t += nthr) {
            int ks = t & 3;
            int nq = (t >> 2) & 15;
            int v  = t >> 6;
            int n0 = nq * 4;
            const float* w = Pw1 + (size_t)v * H;
            float a0 = 0.f, a1 = 0.f, a2 = 0.f, a3 = 0.f;
            for (int k = ks * 4; k < H; k += 16) {
                float4 wv = *(const float4*)(w + k);
                float4 x0 = *(const float4*)(&g_proj[(k + 0) * NB + n0]);
                float4 x1 = *(const float4*)(&g_proj[(k + 1) * NB + n0]);
                float4 x2 = *(const float4*)(&g_proj[(k + 2) * NB + n0]);
                float4 x3 = *(const float4*)(&g_proj[(k + 3) * NB + n0]);
                a0=fmaf(wv.x,x0.x,a0); a1=fmaf(wv.x,x0.y,a1); a2=fmaf(wv.x,x0.z,a2); a3=fmaf(wv.x,x0.w,a3);
                a0=fmaf(wv.y,x1.x,a0); a1=fmaf(wv.y,x1.y,a1); a2=fmaf(wv.y,x1.z,a2); a3=fmaf(wv.y,x1.w,a3);
                a0=fmaf(wv.z,x2.x,a0); a1=fmaf(wv.z,x2.y,a1); a2=fmaf(wv.z,x2.z,a2); a3=fmaf(wv.z,x2.w,a3);
                a0=fmaf(wv.w,x3.x,a0); a1=fmaf(wv.w,x3.y,a1); a2=fmaf(wv.w,x3.z,a2); a3=fmaf(wv.w,x3.w,a3);
            }
            #pragma unroll
            for (int off = 2; off >= 1; off >>= 1) {
                a0 += __shfl_xor_sync(0xFFFFFFFFu, a0, off, 4);
                a1 += __shfl_xor_sync(0xFFFFFFFFu, a1, off, 4);
                a2 += __shfl_xor_sync(0xFFFFFFFFu, a2, off, 4);
                a3 += __shfl_xor_sync(0xFFFFFFFFu, a3, off, 4);
            }
            if (ks == 0) {
                float b = Pb1[v];
                out[((size_t)(n0 + 0) * S + s) * V + v] = a0 + b;
                out[((size_t)(n0 + 1) * S + s) * V + v] = a1 + b;
                out[((size_t)(n0 + 2) * S + s) * V + v] = a2 + b;
                out[((size_t)(n0 + 3) * S + s) * V + v] = a3 + b;
            }
        }
        grid_sync(nb);
    }
}

// ---------------- launcher ----------------
extern "C" void kernel_launch(void* const* d_in, const int* in_sizes, int n_in,
                              void* d_out, int out_size) {
    const float* eo      = (const float*)d_in[0];
    const float* efs     = (const float*)d_in[1];
    const int*   targets = (const int*)  d_in[2];
    const float* embW    = (const float*)d_in[3];
    const float* Qw      = (const float*)d_in[4];
    const float* Qb      = (const float*)d_in[5];
    const float* Kw      = (const float*)d_in[6];
    const float* Kb      = (const float*)d_in[7];
    const float* Vw      = (const float*)d_in[8];
    const float* Vb      = (const float*)d_in[9];
    const float* Wih0    = (const float*)d_in[10];
    const float* Whh0    = (const float*)d_in[11];
    const float* bih0    = (const float*)d_in[12];
    const float* bhh0    = (const float*)d_in[13];
    const float* Wih1    = (const float*)d_in[14];
    const float* Whh1    = (const float*)d_in[15];
    const float* bih1    = (const float*)d_in[16];
    const float* bhh1    = (const float*)d_in[17];
    const float* Pw0     = (const float*)d_in[18];
    const float* Pb0     = (const float*)d_in[19];
    const float* Pw1     = (const float*)d_in[20];
    const float* Pb1     = (const float*)d_in[21];
    float* out = (float*)d_out;

    int smCount = 148;
    cudaDeviceGetAttribute(&smCount, cudaDevAttrMultiProcessorCount, 0);

    prep_hinit<<<(L * NB * H + 255) / 256, 256>>>(efs);
    kproj_gemm<<<dim3(128, 4, 2), 256>>>(eo, Kw, Kb);
    decode_all<<<smCount, 512>>>(eo, targets, embW, Qw, Qb, Vw, Vb,
                                 Wih0, Whh0, bih0, bhh0,
                                 Wih1, Whh1, bih1, bhh1,
                                 Pw0, Pb0, Pw1, Pb1, out);
}